// round 1
// baseline (speedup 1.0000x reference)
#include <cuda_runtime.h>
#include <cuda_bf16.h>

// Problem constants (fixed shapes from reference)
#define NN   50
#define NN2  2500          // N*N
#define ATT  4000          // alpha steps
#define BB   512           // batch
#define PP   32            // features p
#define TT   4000          // mus rows

// Scratch (static __device__ globals: allocation-free rule)
__device__ float g_F[NN2];                       // F = g @ w^2
__device__ float g_fT[(size_t)ATT * NN2];        // fT[t][j][i] = softmax_j(-alpha_t*F[i,j])[i][j]

// ---------------------------------------------------------------------------
// Kernel A: F[r] = sum_c g[r,c] * w[c]^2 ; also write F to output tail
// ---------------------------------------------------------------------------
__global__ void kA_F(const float* __restrict__ g, const float* __restrict__ w,
                     float* __restrict__ outF) {
    int r = blockIdx.x;
    const float* grow = g + (size_t)r * NN2;
    float s = 0.f;
    for (int c = threadIdx.x; c < NN2; c += blockDim.x) {
        float wc = w[c];
        s += grow[c] * (wc * wc);
    }
    __shared__ float red[8];
    #pragma unroll
    for (int o = 16; o; o >>= 1) s += __shfl_down_sync(0xffffffffu, s, o);
    int lane = threadIdx.x & 31, wid = threadIdx.x >> 5;
    if (lane == 0) red[wid] = s;
    __syncthreads();
    if (wid == 0) {
        s = (lane < (blockDim.x >> 5)) ? red[lane] : 0.f;
        #pragma unroll
        for (int o = 4; o; o >>= 1) s += __shfl_down_sync(0xffffffffu, s, o);
        if (lane == 0) { g_F[r] = s; outF[r] = s; }
    }
}

// ---------------------------------------------------------------------------
// Kernel B: build transposed softmax table.
// Block = 4 t-values, 64 threads each (i = row, 50 active).
// fT[t*2500 + j*50 + i] = exp(-a_t*F[i*50+j]) / sum_j exp(-a_t*F[i*50+j])
// Stores are coalesced over i for each j.
// ---------------------------------------------------------------------------
__global__ void kB_softmaxT(const float* __restrict__ alphas) {
    __shared__ float Fs[NN2];
    for (int idx = threadIdx.x; idx < NN2; idx += blockDim.x)
        Fs[idx] = g_F[idx];
    __syncthreads();

    int lt = threadIdx.x >> 6;        // 0..3
    int i  = threadIdx.x & 63;        // row index
    int t  = (blockIdx.x << 2) + lt;
    if (i >= NN) return;              // no further barriers

    float a = alphas[t];
    float e[NN];
    float s = 0.f;
    #pragma unroll
    for (int j = 0; j < NN; j++) {
        float v = __expf(-a * Fs[i * NN + j]);
        e[j] = v;
        s += v;
    }
    float rinv = __fdividef(1.0f, s);
    float* dst = g_fT + (size_t)t * NN2 + i;
    #pragma unroll
    for (int j = 0; j < NN; j++)
        dst[j * NN] = e[j] * rinv;
}

// ---------------------------------------------------------------------------
// Kernel C0: Z[b,i] = P * mus[y_i[b], i]   (initializes atomic accumulator)
// ---------------------------------------------------------------------------
__global__ void kC0_init(const int* __restrict__ y_i, const float* __restrict__ mus,
                         float* __restrict__ Z) {
    int idx = blockIdx.x * blockDim.x + threadIdx.x;
    if (idx >= BB * NN) return;
    int b = idx / NN, i = idx - b * NN;
    Z[idx] = (float)PP * mus[(size_t)y_i[b] * NN + i];
}

// ---------------------------------------------------------------------------
// Kernel C: gather + matvec.
// grid = (B, 8) ; block = 64 ; each block handles 4 p's of one batch b.
// z_i += sum_j fT[t][j][i] * (x[b,j,p] - mus[t,j]) ; atomicAdd into Z.
// fT reads are i-coalesced (200B contiguous per j) and hit L2 (40MB table).
// ---------------------------------------------------------------------------
__global__ void kC_gather(const float* __restrict__ x, const int* __restrict__ x_i,
                          const float* __restrict__ mus, float* __restrict__ Z) {
    int b = blockIdx.x;
    int i = threadIdx.x;          // 0..63, active < 50
    __shared__ float a_s[NN];

    float acc = 0.f;
    int p0 = blockIdx.y << 2;
    for (int pp = 0; pp < 4; pp++) {
        int p = p0 + pp;
        int t = x_i[b * PP + p];
        if (i < NN)
            a_s[i] = x[((size_t)b * NN + i) * PP + p] - mus[(size_t)t * NN + i];
        __syncthreads();
        if (i < NN) {
            const float* fr = g_fT + (size_t)t * NN2 + i;
            float a0 = 0.f, a1 = 0.f, a2 = 0.f, a3 = 0.f, a4 = 0.f;
            #pragma unroll
            for (int j = 0; j < NN; j += 5) {
                a0 += fr[(j + 0) * NN] * a_s[j + 0];
                a1 += fr[(j + 1) * NN] * a_s[j + 1];
                a2 += fr[(j + 2) * NN] * a_s[j + 2];
                a3 += fr[(j + 3) * NN] * a_s[j + 3];
                a4 += fr[(j + 4) * NN] * a_s[j + 4];
            }
            acc += (a0 + a1) + (a2 + a3) + a4;
        }
        __syncthreads();
    }
    if (i < NN) atomicAdd(&Z[b * NN + i], acc);
}

// ---------------------------------------------------------------------------
extern "C" void kernel_launch(void* const* d_in, const int* in_sizes, int n_in,
                              void* d_out, int out_size) {
    const float* x      = (const float*)d_in[0];   // [512,50,32]
    const int*   x_i    = (const int*)  d_in[1];   // [512,32]
    const int*   y_i    = (const int*)  d_in[2];   // [512]
    const float* g      = (const float*)d_in[3];   // [2500,2500]
    const float* w      = (const float*)d_in[4];   // [2500,1]
    const float* mus    = (const float*)d_in[5];   // [4000,50]
    const float* alphas = (const float*)d_in[6];   // [4000,1]

    float* Z    = (float*)d_out;        // [512*50]
    float* outF = Z + BB * NN;          // [2500]

    kA_F<<<NN2, 256>>>(g, w, outF);
    kB_softmaxT<<<ATT / 4, 256>>>(alphas);
    kC0_init<<<(BB * NN + 255) / 256, 256>>>(y_i, mus, Z);
    kC_gather<<<dim3(BB, 8), 64>>>(x, x_i, mus, Z);
}

// round 2
// speedup vs baseline: 1.0286x; 1.0286x over previous
#include <cuda_runtime.h>
#include <cuda_bf16.h>

// Problem constants (fixed shapes from reference)
#define NN   50
#define NN2  2500          // N*N
#define ATT  4000          // alpha steps
#define BB   512           // batch
#define PP   32            // features p
#define TT   4000          // mus rows

// Scratch (static __device__ globals: allocation-free rule)
__device__ float g_F[NN2];                       // F = g @ w^2
__device__ float g_fT[(size_t)ATT * NN2];        // fT[t][j][i] = softmax_j(-alpha_t*F[i,j])[i][j]

// ---------------------------------------------------------------------------
// Kernel A: F[r] = sum_c g[r,c] * w[c]^2 ; also write F to output tail
// ---------------------------------------------------------------------------
__global__ void kA_F(const float* __restrict__ g, const float* __restrict__ w,
                     float* __restrict__ outF) {
    int r = blockIdx.x;
    const float* grow = g + (size_t)r * NN2;
    float s = 0.f;
    for (int c = threadIdx.x; c < NN2; c += blockDim.x) {
        float wc = w[c];
        s += grow[c] * (wc * wc);
    }
    __shared__ float red[8];
    #pragma unroll
    for (int o = 16; o; o >>= 1) s += __shfl_down_sync(0xffffffffu, s, o);
    int lane = threadIdx.x & 31, wid = threadIdx.x >> 5;
    if (lane == 0) red[wid] = s;
    __syncthreads();
    if (wid == 0) {
        s = (lane < (blockDim.x >> 5)) ? red[lane] : 0.f;
        #pragma unroll
        for (int o = 4; o; o >>= 1) s += __shfl_down_sync(0xffffffffu, s, o);
        if (lane == 0) { g_F[r] = s; outF[r] = s; }
    }
}

// ---------------------------------------------------------------------------
// Kernel B: build transposed softmax table.
// Block = 4 t-values, 64 threads each (i = row, 50 active).
// fT[t*2500 + j*50 + i] = exp(-a_t*F[i*50+j]) / sum_j exp(-a_t*F[i*50+j])
// Stores are coalesced over i for each j.
// ---------------------------------------------------------------------------
__global__ void kB_softmaxT(const float* __restrict__ alphas) {
    __shared__ float Fs[NN2];
    for (int idx = threadIdx.x; idx < NN2; idx += blockDim.x)
        Fs[idx] = g_F[idx];
    __syncthreads();

    int lt = threadIdx.x >> 6;        // 0..3
    int i  = threadIdx.x & 63;        // row index
    int t  = (blockIdx.x << 2) + lt;
    if (i >= NN) return;              // no further barriers

    float a = alphas[t];
    float e[NN];
    float s = 0.f;
    #pragma unroll
    for (int j = 0; j < NN; j++) {
        float v = __expf(-a * Fs[i * NN + j]);
        e[j] = v;
        s += v;
    }
    float rinv = __fdividef(1.0f, s);
    float* dst = g_fT + (size_t)t * NN2 + i;
    #pragma unroll
    for (int j = 0; j < NN; j++)
        dst[j * NN] = e[j] * rinv;
}

// ---------------------------------------------------------------------------
// Kernel C0: Z[b,i] = P * mus[y_i[b], i]   (initializes atomic accumulator)
// ---------------------------------------------------------------------------
__global__ void kC0_init(const int* __restrict__ y_i, const float* __restrict__ mus,
                         float* __restrict__ Z) {
    int idx = blockIdx.x * blockDim.x + threadIdx.x;
    if (idx >= BB * NN) return;
    int b = idx / NN, i = idx - b * NN;
    Z[idx] = (float)PP * mus[(size_t)y_i[b] * NN + i];
}

// ---------------------------------------------------------------------------
// Kernel C: gather + matvec.
// grid = (B, 8) ; block = 64 ; each block handles 4 p's of one batch b.
// z_i += sum_j fT[t][j][i] * (x[b,j,p] - mus[t,j]) ; atomicAdd into Z.
// fT reads are i-coalesced (200B contiguous per j) and hit L2 (40MB table).
// ---------------------------------------------------------------------------
__global__ void kC_gather(const float* __restrict__ x, const int* __restrict__ x_i,
                          const float* __restrict__ mus, float* __restrict__ Z) {
    int b = blockIdx.x;
    int i = threadIdx.x;          // 0..63, active < 50
    __shared__ float a_s[NN];

    float acc = 0.f;
    int p0 = blockIdx.y << 2;
    for (int pp = 0; pp < 4; pp++) {
        int p = p0 + pp;
        int t = x_i[b * PP + p];
        if (i < NN)
            a_s[i] = x[((size_t)b * NN + i) * PP + p] - mus[(size_t)t * NN + i];
        __syncthreads();
        if (i < NN) {
            const float* fr = g_fT + (size_t)t * NN2 + i;
            float a0 = 0.f, a1 = 0.f, a2 = 0.f, a3 = 0.f, a4 = 0.f;
            #pragma unroll
            for (int j = 0; j < NN; j += 5) {
                a0 += fr[(j + 0) * NN] * a_s[j + 0];
                a1 += fr[(j + 1) * NN] * a_s[j + 1];
                a2 += fr[(j + 2) * NN] * a_s[j + 2];
                a3 += fr[(j + 3) * NN] * a_s[j + 3];
                a4 += fr[(j + 4) * NN] * a_s[j + 4];
            }
            acc += (a0 + a1) + (a2 + a3) + a4;
        }
        __syncthreads();
    }
    if (i < NN) atomicAdd(&Z[b * NN + i], acc);
}

// ---------------------------------------------------------------------------
extern "C" void kernel_launch(void* const* d_in, const int* in_sizes, int n_in,
                              void* d_out, int out_size) {
    const float* x      = (const float*)d_in[0];   // [512,50,32]
    const int*   x_i    = (const int*)  d_in[1];   // [512,32]
    const int*   y_i    = (const int*)  d_in[2];   // [512]
    const float* g      = (const float*)d_in[3];   // [2500,2500]
    const float* w      = (const float*)d_in[4];   // [2500,1]
    const float* mus    = (const float*)d_in[5];   // [4000,50]
    const float* alphas = (const float*)d_in[6];   // [4000,1]

    float* Z    = (float*)d_out;        // [512*50]
    float* outF = Z + BB * NN;          // [2500]

    kA_F<<<NN2, 256>>>(g, w, outF);
    kB_softmaxT<<<ATT / 4, 256>>>(alphas);
    kC0_init<<<(BB * NN + 255) / 256, 256>>>(y_i, mus, Z);
    kC_gather<<<dim3(BB, 8), 64>>>(x, x_i, mus, Z);
}

// round 3
// speedup vs baseline: 1.2258x; 1.1918x over previous
#include <cuda_runtime.h>
#include <cuda_bf16.h>

// Problem constants (fixed shapes from reference)
#define NN   50
#define NN2  2500          // N*N
#define ATT  4000          // alpha steps
#define BB   512           // batch
#define PP   32            // features p
#define TT   4000          // mus rows

// Scratch (static __device__ globals: allocation-free rule)
__device__ float g_F[NN2];                       // F = g @ w^2
__device__ float g_fT[(size_t)ATT * NN2];        // fT[t][j][i] (i fastest, 50-wide)

// ---------------------------------------------------------------------------
// Kernel A: F[r] = sum_c g[r,c] * w[c]^2 (float4 streamed); also writes F to
// the output tail. Blocks 0..99 additionally initialize Z[b,i] = P*mus[y_i[b],i]
// (independent work folded in to save a launch).
// ---------------------------------------------------------------------------
__global__ void kA_F(const float* __restrict__ g, const float* __restrict__ w,
                     float* __restrict__ outF,
                     const int* __restrict__ y_i, const float* __restrict__ mus,
                     float* __restrict__ Z) {
    int r = blockIdx.x;

    // Folded Z init: 100 blocks x 256 threads cover 512*50 = 25600 elements
    if (r < 100) {
        int idx = r * 256 + threadIdx.x;
        if (idx < BB * NN) {
            int b = idx / NN, i = idx - b * NN;
            Z[idx] = (float)PP * mus[(size_t)y_i[b] * NN + i];
        }
    }

    const float4* grow = (const float4*)(g + (size_t)r * NN2);  // 625 float4
    const float4* w4   = (const float4*)w;
    float s = 0.f;
    for (int c = threadIdx.x; c < NN2 / 4; c += blockDim.x) {
        float4 gv = grow[c];
        float4 wv = w4[c];
        s += gv.x * (wv.x * wv.x) + gv.y * (wv.y * wv.y)
           + gv.z * (wv.z * wv.z) + gv.w * (wv.w * wv.w);
    }
    __shared__ float red[8];
    #pragma unroll
    for (int o = 16; o; o >>= 1) s += __shfl_down_sync(0xffffffffu, s, o);
    int lane = threadIdx.x & 31, wid = threadIdx.x >> 5;
    if (lane == 0) red[wid] = s;
    __syncthreads();
    if (wid == 0) {
        s = (lane < (blockDim.x >> 5)) ? red[lane] : 0.f;
        #pragma unroll
        for (int o = 4; o; o >>= 1) s += __shfl_down_sync(0xffffffffu, s, o);
        if (lane == 0) { g_F[r] = s; outF[r] = s; }
    }
}

// ---------------------------------------------------------------------------
// Kernel B: build transposed softmax table.
// Block = 4 t-values, 64 threads each (i = row, 50 active).
// fT[t*2500 + j*50 + i] = exp(-a_t*F[i*50+j]) / sum_j exp(-a_t*F[i*50+j])
// Stores are coalesced over i for each j.
// ---------------------------------------------------------------------------
__global__ void kB_softmaxT(const float* __restrict__ alphas) {
    __shared__ float Fs[NN2];
    for (int idx = threadIdx.x; idx < NN2; idx += blockDim.x)
        Fs[idx] = g_F[idx];
    __syncthreads();

    int lt = threadIdx.x >> 6;        // 0..3
    int i  = threadIdx.x & 63;        // row index
    int t  = (blockIdx.x << 2) + lt;
    if (i >= NN) return;              // no further barriers

    float a = alphas[t];
    float e[NN];
    float s = 0.f;
    #pragma unroll
    for (int j = 0; j < NN; j++) {
        float v = __expf(-a * Fs[i * NN + j]);
        e[j] = v;
        s += v;
    }
    float rinv = __fdividef(1.0f, s);
    float* dst = g_fT + (size_t)t * NN2 + i;
    #pragma unroll
    for (int j = 0; j < NN; j++)
        dst[j * NN] = e[j] * rinv;
}

// ---------------------------------------------------------------------------
// Kernel C: gather + matvec, warp-per-(b,p), float2 over i.
// grid = (B, 8), block = 128 (4 warps; warp w handles p = 4*blockIdx.y + w).
// Lane l (<25) owns i = {2l, 2l+1}: reads fT as float2 with stride 25 per j.
// All 200B of each j-row are consumed; half the LDG issues of the scalar form.
// ---------------------------------------------------------------------------
__global__ void kC_gather(const float* __restrict__ x, const int* __restrict__ x_i,
                          const float* __restrict__ mus, float* __restrict__ Z) {
    int b    = blockIdx.x;
    int w    = threadIdx.x >> 5;
    int lane = threadIdx.x & 31;
    int p    = (blockIdx.y << 2) + w;

    __shared__ float a_s[4][52];

    int t = x_i[b * PP + p];
    if (lane < NN)
        a_s[w][lane] = x[((size_t)b * NN + lane) * PP + p] - mus[(size_t)t * NN + lane];
    int i2 = lane + 32;
    if (i2 < NN)
        a_s[w][i2] = x[((size_t)b * NN + i2) * PP + p] - mus[(size_t)t * NN + i2];
    __syncwarp();

    if (lane < 25) {
        const float2* fr = (const float2*)(g_fT + (size_t)t * NN2) + lane;  // +25 per j
        float2 acc0 = {0.f, 0.f}, acc1 = {0.f, 0.f};
        #pragma unroll
        for (int j = 0; j < NN; j += 2) {
            float a0 = a_s[w][j], a1 = a_s[w][j + 1];
            float2 f0 = fr[(j + 0) * 25];
            float2 f1 = fr[(j + 1) * 25];
            acc0.x += f0.x * a0; acc0.y += f0.y * a0;
            acc1.x += f1.x * a1; acc1.y += f1.y * a1;
        }
        atomicAdd(&Z[b * NN + 2 * lane],     acc0.x + acc1.x);
        atomicAdd(&Z[b * NN + 2 * lane + 1], acc0.y + acc1.y);
    }
}

// ---------------------------------------------------------------------------
extern "C" void kernel_launch(void* const* d_in, const int* in_sizes, int n_in,
                              void* d_out, int out_size) {
    const float* x      = (const float*)d_in[0];   // [512,50,32]
    const int*   x_i    = (const int*)  d_in[1];   // [512,32]
    const int*   y_i    = (const int*)  d_in[2];   // [512]
    const float* g      = (const float*)d_in[3];   // [2500,2500]
    const float* w      = (const float*)d_in[4];   // [2500,1]
    const float* mus    = (const float*)d_in[5];   // [4000,50]
    const float* alphas = (const float*)d_in[6];   // [4000,1]

    float* Z    = (float*)d_out;        // [512*50]
    float* outF = Z + BB * NN;          // [2500]

    kA_F<<<NN2, 256>>>(g, w, outF, y_i, mus, Z);
    kB_softmaxT<<<ATT / 4, 256>>>(alphas);
    kC_gather<<<dim3(BB, 8), 128>>>(x, x_i, mus, Z);
}